// round 1
// baseline (speedup 1.0000x reference)
#include <cuda_runtime.h>
#include <cuda_bf16.h>
#include <cstdint>

// Problem constants (B=2, H=16, L=2048, DK=DV=128)
namespace {
constexpr int Lc  = 2048;
constexpr int Hc  = 16;
constexpr int Bc  = 2;
constexpr int DKc = 128;
constexpr int DVc = 128;
constexpr int BM  = 64;   // Q rows per CTA
constexpr int BN  = 64;   // K/V rows per iteration
constexpr int SPAD = 68;  // padded stride (floats), keeps float4 alignment, avoids bank conflicts
constexpr int NTHREADS = 256;

// smem layout (floats): QsT[128][68] | KsT[128][68] | Vs[64][128] | Ss[64][68] | Cs[64]
constexpr int SMEM_FLOATS = 2 * DKc * SPAD + BN * DVc + BM * SPAD + 64;
}

__global__ __launch_bounds__(NTHREADS, 1)
void retnet_fused_kernel(const float* __restrict__ q,
                         const float* __restrict__ k,
                         const float* __restrict__ v,
                         float* __restrict__ out)
{
    extern __shared__ float sm[];
    float* QsT = sm;                       // [DK][SPAD]  Q transposed
    float* KsT = QsT + DKc * SPAD;         // [DK][SPAD]  K transposed, pre-scaled by gamma^{-j}
    float* Vs  = KsT + DKc * SPAD;         // [BN][DV]
    float* Ss  = Vs  + BN * DVc;           // [BM][SPAD]  decayed scores
    float* Cs  = Ss  + BM * SPAD;          // [BN]        gamma^{-j_local}

    const int tid = threadIdx.x;
    const int tx  = tid & 15;   // 16 col-groups
    const int ty  = tid >> 4;   // 16 row-groups

    const int bh = blockIdx.y;        // 0..31
    const int b  = bh >> 4;
    const int h  = bh & 15;
    // heavy (large-m) row blocks first for better wave balance
    const int m_block = (int)(gridDim.x - 1) - (int)blockIdx.x;
    const int i0 = m_block * BM;

    const float* qb = q + (size_t)bh * Lc * DKc;
    const float* kb = k + (size_t)bh * Lc * DKc;
    const float* vb = v + (size_t)bh * Lc * DVc;

    // log2(gamma_h) computed accurately: gamma = 1 - 2^{-5-h}
    const float lg2 = log1pf(-exp2f(-5.0f - (float)h)) * 1.4426950408889634f;

    // Cs[j] = gamma^{-j}, iteration-invariant (j is local 0..63)
    if (tid < BN) Cs[tid] = exp2f(-lg2 * (float)tid);

    // Load Q tile transposed: QsT[kk][i]   (one-time per CTA)
    #pragma unroll
    for (int t = 0; t < (BM * DKc / 4) / NTHREADS; t++) {
        int idx = tid + t * NTHREADS;
        int i   = idx & (BM - 1);
        int kk4 = idx >> 6;                 // 0..31
        float4 g = *(const float4*)(qb + (size_t)(i0 + i) * DKc + kk4 * 4);
        QsT[(kk4 * 4 + 0) * SPAD + i] = g.x;
        QsT[(kk4 * 4 + 1) * SPAD + i] = g.y;
        QsT[(kk4 * 4 + 2) * SPAD + i] = g.z;
        QsT[(kk4 * 4 + 3) * SPAD + i] = g.w;
    }

    float acc[4][8];
    #pragma unroll
    for (int r = 0; r < 4; r++)
        #pragma unroll
        for (int c = 0; c < 8; c++) acc[r][c] = 0.0f;

    float rowsum[4] = {0.0f, 0.0f, 0.0f, 0.0f};

    // Row decay factors: start at diagonal block (delta = 0): R_i = gamma^{i_local}
    // Each iteration moves j0 down by BN -> multiply by gamma^{BN} (shrinks, no overflow)
    float Rr[4];
    #pragma unroll
    for (int r = 0; r < 4; r++) Rr[r] = exp2f(lg2 * (float)(ty * 4 + r));
    const float gstep = exp2f(lg2 * (float)BN);

    __syncthreads();

    for (int j0 = i0; j0 >= 0; j0 -= BN) {
        // ---- load K^T (scaled by gamma^{-j}) and V for this j-block ----
        #pragma unroll
        for (int t = 0; t < (BN * DKc / 4) / NTHREADS; t++) {
            int idx = tid + t * NTHREADS;
            int j   = idx & (BN - 1);
            int kk4 = idx >> 6;
            float cj = Cs[j];
            float4 g = *(const float4*)(kb + (size_t)(j0 + j) * DKc + kk4 * 4);
            KsT[(kk4 * 4 + 0) * SPAD + j] = g.x * cj;
            KsT[(kk4 * 4 + 1) * SPAD + j] = g.y * cj;
            KsT[(kk4 * 4 + 2) * SPAD + j] = g.z * cj;
            KsT[(kk4 * 4 + 3) * SPAD + j] = g.w * cj;
        }
        #pragma unroll
        for (int t = 0; t < (BN * DVc / 4) / NTHREADS; t++) {
            int idx = tid + t * NTHREADS;
            int j   = idx >> 5;             // 0..63
            int d4  = idx & 31;             // 0..31
            *(float4*)(Vs + j * DVc + d4 * 4) =
                *(const float4*)(vb + (size_t)(j0 + j) * DVc + d4 * 4);
        }
        __syncthreads();

        // ---- GEMM1: S = Q K'^T (K' already carries gamma^{-j}) ----
        float s[4][4];
        #pragma unroll
        for (int r = 0; r < 4; r++)
            #pragma unroll
            for (int c = 0; c < 4; c++) s[r][c] = 0.0f;

        #pragma unroll 4
        for (int kk = 0; kk < DKc; kk++) {
            float4 a4 = *(const float4*)(QsT + kk * SPAD + (ty << 2));
            float4 b4 = *(const float4*)(KsT + kk * SPAD + (tx << 2));
            float av[4] = {a4.x, a4.y, a4.z, a4.w};
            float bv[4] = {b4.x, b4.y, b4.z, b4.w};
            #pragma unroll
            for (int r = 0; r < 4; r++)
                #pragma unroll
                for (int c = 0; c < 4; c++)
                    s[r][c] += av[r] * bv[c];
        }

        // apply row decay gamma^{delta + i}, causal mask on diagonal block,
        // accumulate row sums, stage S to smem
        const bool diag = (j0 == i0);
        #pragma unroll
        for (int r = 0; r < 4; r++) {
            const float ri = Rr[r];
            #pragma unroll
            for (int c = 0; c < 4; c++) {
                float val = s[r][c] * ri;
                if (diag && (tx * 4 + c > ty * 4 + r)) val = 0.0f;
                rowsum[r] += val;
                Ss[(ty * 4 + r) * SPAD + tx * 4 + c] = val;
            }
        }
        #pragma unroll
        for (int r = 0; r < 4; r++) Rr[r] *= gstep;
        __syncthreads();

        // ---- GEMM2: acc += S @ V ----
        #pragma unroll 2
        for (int j = 0; j < BN; j++) {
            float4 v0 = *(const float4*)(Vs + j * DVc + (tx << 3));
            float4 v1 = *(const float4*)(Vs + j * DVc + (tx << 3) + 4);
            #pragma unroll
            for (int r = 0; r < 4; r++) {
                float sv = Ss[(ty * 4 + r) * SPAD + j];
                acc[r][0] += sv * v0.x;
                acc[r][1] += sv * v0.y;
                acc[r][2] += sv * v0.z;
                acc[r][3] += sv * v0.w;
                acc[r][4] += sv * v1.x;
                acc[r][5] += sv * v1.y;
                acc[r][6] += sv * v1.z;
                acc[r][7] += sv * v1.w;
            }
        }
        __syncthreads();
    }

    // ---- reduce row sums across the 16 column-lanes (xor stays inside 16-lane group) ----
    #pragma unroll
    for (int off = 1; off < 16; off <<= 1) {
        #pragma unroll
        for (int r = 0; r < 4; r++)
            rowsum[r] += __shfl_xor_sync(0xffffffffu, rowsum[r], off);
    }

    // ---- normalize by clipped |rowsum|, then RMSNorm over DV ----
    float ssq[4] = {0.0f, 0.0f, 0.0f, 0.0f};
    #pragma unroll
    for (int r = 0; r < 4; r++) {
        const float inv_dn = 1.0f / fmaxf(fabsf(rowsum[r]), 1.0f);
        #pragma unroll
        for (int c = 0; c < 8; c++) {
            float y = acc[r][c] * inv_dn;
            acc[r][c] = y;
            ssq[r] += y * y;
        }
    }
    #pragma unroll
    for (int off = 1; off < 16; off <<= 1) {
        #pragma unroll
        for (int r = 0; r < 4; r++)
            ssq[r] += __shfl_xor_sync(0xffffffffu, ssq[r], off);
    }

    // ---- write out[b, i, h, d] with fused RMS scale (coalesced float4) ----
    #pragma unroll
    for (int r = 0; r < 4; r++) {
        const float sc = rsqrtf(ssq[r] * (1.0f / (float)DVc) + 1e-6f);
        const int gi = i0 + ty * 4 + r;
        float* po = out + (((size_t)b * Lc + gi) * Hc + h) * DVc + (tx << 3);
        float4 o0, o1;
        o0.x = acc[r][0] * sc; o0.y = acc[r][1] * sc;
        o0.z = acc[r][2] * sc; o0.w = acc[r][3] * sc;
        o1.x = acc[r][4] * sc; o1.y = acc[r][5] * sc;
        o1.z = acc[r][6] * sc; o1.w = acc[r][7] * sc;
        *(float4*)(po + 0) = o0;
        *(float4*)(po + 4) = o1;
    }
}

extern "C" void kernel_launch(void* const* d_in, const int* in_sizes, int n_in,
                              void* d_out, int out_size)
{
    // inputs: q, k, v, decay_mask (unused, computed analytically), intra_decay (unused)
    const float* q = (const float*)d_in[0];
    const float* k = (const float*)d_in[1];
    const float* v = (const float*)d_in[2];
    float* out = (float*)d_out;

    const size_t smem_bytes = (size_t)SMEM_FLOATS * sizeof(float);
    cudaFuncSetAttribute(retnet_fused_kernel,
                         cudaFuncAttributeMaxDynamicSharedMemorySize,
                         (int)smem_bytes);

    dim3 grid(Lc / BM, Bc * Hc);   // (32, 32): x = row block (reversed in-kernel), y = (b,h)
    retnet_fused_kernel<<<grid, NTHREADS, smem_bytes>>>(q, k, v, out);
}

// round 2
// speedup vs baseline: 3.6438x; 3.6438x over previous
#include <cuda_runtime.h>
#include <cuda_bf16.h>
#include <cstdint>

// RetNet parallel-form retention, fused, tf32 mma.sync tensor-core version.
// B=2, H=16, L=2048, DK=DV=128.
namespace {
constexpr int Lc  = 2048;
constexpr int Hc  = 16;
constexpr int Bc  = 2;
constexpr int DKc = 128;
constexpr int DVc = 128;
constexpr int BM  = 64;    // Q rows per CTA
constexpr int BN  = 64;    // K/V rows per j-iteration
constexpr int QS_STRIDE = 132;   // (4*lr + lc) mod 32 unique -> conflict-free frags
constexpr int KS_STRIDE = 132;
constexpr int VS_STRIDE = 136;   // (8*lc + lr) mod 32 unique
constexpr int SS_STRIDE = 72;    // (8*lr + lc) mod 32 unique
constexpr int NTHREADS  = 256;

constexpr int SMEM_FLOATS =
    BM * QS_STRIDE + BN * KS_STRIDE + BN * VS_STRIDE + BM * SS_STRIDE + BM + BM;
}

__device__ __forceinline__ float f2tf32f(float x) {
    uint32_t r;
    asm("cvt.rna.tf32.f32 %0, %1;" : "=r"(r) : "f"(x));
    return __uint_as_float(r);
}

__device__ __forceinline__ void mma_tf32(float c[4],
                                         uint32_t a0, uint32_t a1, uint32_t a2, uint32_t a3,
                                         uint32_t b0, uint32_t b1) {
    asm volatile(
        "mma.sync.aligned.m16n8k8.row.col.f32.tf32.tf32.f32 "
        "{%0,%1,%2,%3}, {%4,%5,%6,%7}, {%8,%9}, {%0,%1,%2,%3};\n"
        : "+f"(c[0]), "+f"(c[1]), "+f"(c[2]), "+f"(c[3])
        : "r"(a0), "r"(a1), "r"(a2), "r"(a3), "r"(b0), "r"(b1));
}

#define F2U __float_as_uint

__global__ __launch_bounds__(NTHREADS, 1)
void retnet_mma_kernel(const float* __restrict__ q,
                       const float* __restrict__ k,
                       const float* __restrict__ v,
                       float* __restrict__ out)
{
    extern __shared__ float sm[];
    float* Qs  = sm;                        // [BM][132] tf32
    float* Ks  = Qs  + BM * QS_STRIDE;      // [BN][132] tf32, pre-scaled by gamma^{-j}
    float* Vs  = Ks  + BN * KS_STRIDE;      // [BN][136] tf32
    float* Ss  = Vs  + BN * VS_STRIDE;      // [BM][72]  tf32 decayed scores
    float* RSs = Ss  + BM * SS_STRIDE;      // [BM] rowsum
    float* SQs = RSs + BM;                  // [BM] sum of squares

    const int tid  = threadIdx.x;
    const int lane = tid & 31;
    const int warp = tid >> 5;
    const int wm   = warp >> 1;   // 0..3 : 16-row group
    const int wn   = warp & 1;    // 0..1 : column half
    const int lr   = lane >> 2;   // 0..7
    const int lc   = lane & 3;    // 0..3

    const int bh = blockIdx.y;
    const int b  = bh >> 4;
    const int h  = bh & 15;
    const int m_block = (int)(gridDim.x - 1) - (int)blockIdx.x;  // heavy blocks first
    const int i0 = m_block * BM;

    const float* qb = q + (size_t)bh * Lc * DKc;
    const float* kb = k + (size_t)bh * Lc * DKc;
    const float* vb = v + (size_t)bh * Lc * DVc;

    // log2(gamma_h), gamma = 1 - 2^{-5-h}
    const float lg2 = log1pf(-exp2f(-5.0f - (float)h)) * 1.4426950408889634f;

    // ---- stage Q tile (tf32) ----
    #pragma unroll
    for (int t = 0; t < (BM * DKc / 4) / NTHREADS; t++) {
        int idx = tid + t * NTHREADS;
        int r   = idx >> 5;        // 0..63
        int c4  = idx & 31;        // 0..31
        float4 g = *(const float4*)(qb + (size_t)(i0 + r) * DKc + c4 * 4);
        float* p = Qs + r * QS_STRIDE + c4 * 4;
        float4 o;
        o.x = f2tf32f(g.x); o.y = f2tf32f(g.y);
        o.z = f2tf32f(g.z); o.w = f2tf32f(g.w);
        *(float4*)p = o;
    }

    float oc[8][4];
    #pragma unroll
    for (int t = 0; t < 8; t++)
        #pragma unroll
        for (int e = 0; e < 4; e++) oc[t][e] = 0.0f;

    float rs0 = 0.0f, rs1 = 0.0f;

    const int il0 = wm * 16 + lr;      // local row of c0/c1
    const int il1 = il0 + 8;           // local row of c2/c3
    float R0 = exp2f(lg2 * (float)il0);
    float R1 = exp2f(lg2 * (float)il1);
    const float gstep = exp2f(lg2 * (float)BN);

    __syncthreads();

    for (int j0 = i0; j0 >= 0; j0 -= BN) {
        // ---- stage K (scaled by gamma^{-j_local}) and V, both tf32 ----
        #pragma unroll
        for (int t = 0; t < (BN * DKc / 4) / NTHREADS; t++) {
            int idx = tid + t * NTHREADS;
            int r   = idx >> 5;
            int c4  = idx & 31;
            float cj = exp2f(-lg2 * (float)r);
            float4 g = *(const float4*)(kb + (size_t)(j0 + r) * DKc + c4 * 4);
            float4 o;
            o.x = f2tf32f(g.x * cj); o.y = f2tf32f(g.y * cj);
            o.z = f2tf32f(g.z * cj); o.w = f2tf32f(g.w * cj);
            *(float4*)(Ks + r * KS_STRIDE + c4 * 4) = o;
        }
        #pragma unroll
        for (int t = 0; t < (BN * DVc / 4) / NTHREADS; t++) {
            int idx = tid + t * NTHREADS;
            int r   = idx >> 5;
            int c4  = idx & 31;
            float4 g = *(const float4*)(vb + (size_t)(j0 + r) * DVc + c4 * 4);
            float4 o;
            o.x = f2tf32f(g.x); o.y = f2tf32f(g.y);
            o.z = f2tf32f(g.z); o.w = f2tf32f(g.w);
            *(float4*)(Vs + r * VS_STRIDE + c4 * 4) = o;
        }
        __syncthreads();

        // ---- GEMM1: S(64x64) = Q K'^T via tf32 mma ----
        float sc[4][4];
        #pragma unroll
        for (int t = 0; t < 4; t++)
            #pragma unroll
            for (int e = 0; e < 4; e++) sc[t][e] = 0.0f;

        #pragma unroll
        for (int ks = 0; ks < DKc / 8; ks++) {
            const int kk = ks * 8;
            uint32_t a0 = F2U(Qs[il0 * QS_STRIDE + kk + lc]);
            uint32_t a1 = F2U(Qs[il1 * QS_STRIDE + kk + lc]);
            uint32_t a2 = F2U(Qs[il0 * QS_STRIDE + kk + lc + 4]);
            uint32_t a3 = F2U(Qs[il1 * QS_STRIDE + kk + lc + 4]);
            #pragma unroll
            for (int t = 0; t < 4; t++) {
                const int n = wn * 32 + t * 8;
                uint32_t b0 = F2U(Ks[(n + lr) * KS_STRIDE + kk + lc]);
                uint32_t b1 = F2U(Ks[(n + lr) * KS_STRIDE + kk + lc + 4]);
                mma_tf32(sc[t], a0, a1, a2, a3, b0, b1);
            }
        }

        // ---- decay + causal mask + rowsum, stage S (tf32) ----
        const bool diag = (j0 == i0);
        #pragma unroll
        for (int t = 0; t < 4; t++) {
            const int jb = wn * 32 + t * 8 + 2 * lc;   // col of c0
            float v0 = sc[t][0] * R0;
            float v1 = sc[t][1] * R0;
            float v2 = sc[t][2] * R1;
            float v3 = sc[t][3] * R1;
            if (diag) {
                if (jb     > il0) v0 = 0.0f;
                if (jb + 1 > il0) v1 = 0.0f;
                if (jb     > il1) v2 = 0.0f;
                if (jb + 1 > il1) v3 = 0.0f;
            }
            rs0 += v0 + v1;
            rs1 += v2 + v3;
            Ss[il0 * SS_STRIDE + jb]     = f2tf32f(v0);
            Ss[il0 * SS_STRIDE + jb + 1] = f2tf32f(v1);
            Ss[il1 * SS_STRIDE + jb]     = f2tf32f(v2);
            Ss[il1 * SS_STRIDE + jb + 1] = f2tf32f(v3);
        }
        R0 *= gstep;
        R1 *= gstep;
        __syncthreads();

        // ---- GEMM2: O(64x128) += S @ V via tf32 mma ----
        #pragma unroll
        for (int ks = 0; ks < BN / 8; ks++) {
            const int kk = ks * 8;
            uint32_t a0 = F2U(Ss[il0 * SS_STRIDE + kk + lc]);
            uint32_t a1 = F2U(Ss[il1 * SS_STRIDE + kk + lc]);
            uint32_t a2 = F2U(Ss[il0 * SS_STRIDE + kk + lc + 4]);
            uint32_t a3 = F2U(Ss[il1 * SS_STRIDE + kk + lc + 4]);
            #pragma unroll
            for (int t = 0; t < 8; t++) {
                const int n = wn * 64 + t * 8;
                uint32_t b0 = F2U(Vs[(kk + lc) * VS_STRIDE + n + lr]);
                uint32_t b1 = F2U(Vs[(kk + lc + 4) * VS_STRIDE + n + lr]);
                mma_tf32(oc[t], a0, a1, a2, a3, b0, b1);
            }
        }
        __syncthreads();   // before next iteration overwrites Ks/Vs/Ss
    }

    // ---- reduce rowsums: across lane quad (cols), then across the two wn warps ----
    rs0 += __shfl_xor_sync(0xffffffffu, rs0, 1);
    rs0 += __shfl_xor_sync(0xffffffffu, rs0, 2);
    rs1 += __shfl_xor_sync(0xffffffffu, rs1, 1);
    rs1 += __shfl_xor_sync(0xffffffffu, rs1, 2);

    if (wn == 0 && lc == 0) { RSs[il0] = rs0; RSs[il1] = rs1; }
    __syncthreads();
    if (wn == 1 && lc == 0) { RSs[il0] += rs0; RSs[il1] += rs1; }
    __syncthreads();

    const float dn0 = 1.0f / fmaxf(fabsf(RSs[il0]), 1.0f);
    const float dn1 = 1.0f / fmaxf(fabsf(RSs[il1]), 1.0f);

    // ---- normalize, RMSNorm sum-of-squares ----
    float ssq0 = 0.0f, ssq1 = 0.0f;
    #pragma unroll
    for (int t = 0; t < 8; t++) {
        oc[t][0] *= dn0; oc[t][1] *= dn0;
        oc[t][2] *= dn1; oc[t][3] *= dn1;
        ssq0 += oc[t][0] * oc[t][0] + oc[t][1] * oc[t][1];
        ssq1 += oc[t][2] * oc[t][2] + oc[t][3] * oc[t][3];
    }
    ssq0 += __shfl_xor_sync(0xffffffffu, ssq0, 1);
    ssq0 += __shfl_xor_sync(0xffffffffu, ssq0, 2);
    ssq1 += __shfl_xor_sync(0xffffffffu, ssq1, 1);
    ssq1 += __shfl_xor_sync(0xffffffffu, ssq1, 2);

    if (wn == 0 && lc == 0) { SQs[il0] = ssq0; SQs[il1] = ssq1; }
    __syncthreads();
    if (wn == 1 && lc == 0) { SQs[il0] += ssq0; SQs[il1] += ssq1; }
    __syncthreads();

    const float sc0 = rsqrtf(SQs[il0] * (1.0f / (float)DVc) + 1e-6f);
    const float sc1 = rsqrtf(SQs[il1] * (1.0f / (float)DVc) + 1e-6f);

    // ---- write out[b, i, h, d] ----
    const int gi0 = i0 + il0;
    const int gi1 = i0 + il1;
    float* po0 = out + (((size_t)b * Lc + gi0) * Hc + h) * DVc;
    float* po1 = out + (((size_t)b * Lc + gi1) * Hc + h) * DVc;
    #pragma unroll
    for (int t = 0; t < 8; t++) {
        const int d = wn * 64 + t * 8 + 2 * lc;
        float2 w0, w1;
        w0.x = oc[t][0] * sc0; w0.y = oc[t][1] * sc0;
        w1.x = oc[t][2] * sc1; w1.y = oc[t][3] * sc1;
        *(float2*)(po0 + d) = w0;
        *(float2*)(po1 + d) = w1;
    }
}

extern "C" void kernel_launch(void* const* d_in, const int* in_sizes, int n_in,
                              void* d_out, int out_size)
{
    const float* q = (const float*)d_in[0];
    const float* k = (const float*)d_in[1];
    const float* v = (const float*)d_in[2];
    float* out = (float*)d_out;

    const size_t smem_bytes = (size_t)SMEM_FLOATS * sizeof(float);
    cudaFuncSetAttribute(retnet_mma_kernel,
                         cudaFuncAttributeMaxDynamicSharedMemorySize,
                         (int)smem_bytes);

    dim3 grid(Lc / BM, Bc * Hc);   // (32, 32)
    retnet_mma_kernel<<<grid, NTHREADS, smem_bytes>>>(q, k, v, out);
}